// round 8
// baseline (speedup 1.0000x reference)
#include <cuda_runtime.h>

#define N_TOK   262144
#define NH      256
#define NE      4
#define BM      128
#define BN      128
#define BK      32

// ---------------- scratch (static device globals; no allocation) ----------------
__device__ float g_h[(size_t)N_TOK * NH];      // 256 MB intermediate h
__device__ float g_gate[N_TOK];
__device__ int   g_eid[N_TOK];
__device__ int   g_pos[N_TOK];
__device__ int   g_cnt[NE];
__device__ int   g_off[NE + 1];
__device__ int   g_perm[N_TOK + NE * BM];

// ---------------- packed-f32x2 helpers ----------------
__device__ __forceinline__ unsigned long long pack2(float x) {
    unsigned long long r;
    asm("mov.b64 %0, {%1, %1};" : "=l"(r) : "r"(__float_as_uint(x)));
    return r;
}
__device__ __forceinline__ void fma2(unsigned long long& acc,
                                     unsigned long long a, unsigned long long b) {
    asm("fma.rn.f32x2 %0, %1, %2, %0;" : "+l"(acc) : "l"(a), "l"(b));
}
__device__ __forceinline__ float2 unpack2(unsigned long long v) {
    unsigned lo, hi;
    asm("mov.b64 {%0, %1}, %2;" : "=r"(lo), "=r"(hi) : "l"(v));
    float2 f;
    f.x = __uint_as_float(lo);
    f.y = __uint_as_float(hi);
    return f;
}

// ---------------- init ----------------
__global__ void k_zero() {
    if (threadIdx.x < NE) g_cnt[threadIdx.x] = 0;
}

// ---------------- stage 1: h = x @ W1 + b1 ----------------
__global__ void __launch_bounds__(256, 2) k_stage1(
    const float* __restrict__ x, const float* __restrict__ W1,
    const float* __restrict__ b1)
{
    __shared__ __align__(16) float As[BK][BM + 4];   // 132 floats/row: 528B, 16B-aligned rows
    __shared__ __align__(16) float Bs[BK][BN];

    const int m0 = blockIdx.x * BM;
    const int n0 = blockIdx.y * BN;
    const int tid = threadIdx.x;
    const int tx = tid & 15;        // output col group
    const int ty = tid >> 4;        // output row group
    const int ar = tid >> 3;        // A-load row base (0..31)
    const int ac4 = tid & 7;        // A-load k-quad (0..7)
    const int br = tid >> 5;        // B-load k-row base (0..7)
    const int bc4 = tid & 31;       // B-load col-quad (0..31)

    unsigned long long acc[8][4];
#pragma unroll
    for (int i = 0; i < 8; i++)
#pragma unroll
        for (int j = 0; j < 4; j++) acc[i][j] = 0ull;

    for (int kt = 0; kt < NH / BK; kt++) {
        // A tile: x[m0..m0+127][kt*32..+31], stored transposed As[k][row]
#pragma unroll
        for (int i = 0; i < 4; i++) {
            int r = ar + i * 32;
            float4 v = *(const float4*)(x + (size_t)(m0 + r) * NH + kt * BK + ac4 * 4);
            As[ac4 * 4 + 0][r] = v.x;
            As[ac4 * 4 + 1][r] = v.y;
            As[ac4 * 4 + 2][r] = v.z;
            As[ac4 * 4 + 3][r] = v.w;
        }
        // B tile: W1[kt*32+kr][n0..n0+127], natural layout Bs[k][col]
#pragma unroll
        for (int i = 0; i < 4; i++) {
            int kr = br + i * 8;
            *(float4*)&Bs[kr][bc4 * 4] =
                *(const float4*)(W1 + (size_t)(kt * BK + kr) * NH + n0 + bc4 * 4);
        }
        __syncthreads();

#pragma unroll
        for (int kk = 0; kk < BK; kk++) {
            const float4 a0 = *(const float4*)&As[kk][ty * 8];
            const float4 a1 = *(const float4*)&As[kk][ty * 8 + 4];
            const ulonglong2 bb0 = *(const ulonglong2*)&Bs[kk][tx * 8];
            const ulonglong2 bb1 = *(const ulonglong2*)&Bs[kk][tx * 8 + 4];
            unsigned long long pa;
            pa = pack2(a0.x); fma2(acc[0][0], pa, bb0.x); fma2(acc[0][1], pa, bb0.y); fma2(acc[0][2], pa, bb1.x); fma2(acc[0][3], pa, bb1.y);
            pa = pack2(a0.y); fma2(acc[1][0], pa, bb0.x); fma2(acc[1][1], pa, bb0.y); fma2(acc[1][2], pa, bb1.x); fma2(acc[1][3], pa, bb1.y);
            pa = pack2(a0.z); fma2(acc[2][0], pa, bb0.x); fma2(acc[2][1], pa, bb0.y); fma2(acc[2][2], pa, bb1.x); fma2(acc[2][3], pa, bb1.y);
            pa = pack2(a0.w); fma2(acc[3][0], pa, bb0.x); fma2(acc[3][1], pa, bb0.y); fma2(acc[3][2], pa, bb1.x); fma2(acc[3][3], pa, bb1.y);
            pa = pack2(a1.x); fma2(acc[4][0], pa, bb0.x); fma2(acc[4][1], pa, bb0.y); fma2(acc[4][2], pa, bb1.x); fma2(acc[4][3], pa, bb1.y);
            pa = pack2(a1.y); fma2(acc[5][0], pa, bb0.x); fma2(acc[5][1], pa, bb0.y); fma2(acc[5][2], pa, bb1.x); fma2(acc[5][3], pa, bb1.y);
            pa = pack2(a1.z); fma2(acc[6][0], pa, bb0.x); fma2(acc[6][1], pa, bb0.y); fma2(acc[6][2], pa, bb1.x); fma2(acc[6][3], pa, bb1.y);
            pa = pack2(a1.w); fma2(acc[7][0], pa, bb0.x); fma2(acc[7][1], pa, bb0.y); fma2(acc[7][2], pa, bb1.x); fma2(acc[7][3], pa, bb1.y);
        }
        __syncthreads();
    }

    float bias[8];
#pragma unroll
    for (int j = 0; j < 8; j++) bias[j] = b1[n0 + tx * 8 + j];

#pragma unroll
    for (int i = 0; i < 8; i++) {
        int row = m0 + ty * 8 + i;
        float o[8];
#pragma unroll
        for (int jp = 0; jp < 4; jp++) {
            float2 v = unpack2(acc[i][jp]);
            o[2 * jp]     = v.x + bias[2 * jp];
            o[2 * jp + 1] = v.y + bias[2 * jp + 1];
        }
        float4* dst = (float4*)(g_h + (size_t)row * NH + n0 + tx * 8);
        dst[0] = make_float4(o[0], o[1], o[2], o[3]);
        dst[1] = make_float4(o[4], o[5], o[6], o[7]);
    }
}

// ---------------- routing: logits, softmax, argmax, bucket counts ----------------
// One block = 8 warps, each warp handles 16 tokens -> 128 tokens/block.
__global__ void k_route(const float* __restrict__ Wg) {
    __shared__ float wg_s[NH * NE];
    const int tid = threadIdx.x;
    for (int i = tid; i < NH * NE; i += 256) wg_s[i] = Wg[i];
    __syncthreads();

    const int wid = tid >> 5;
    const int lane = tid & 31;
    const int warp_global = blockIdx.x * 8 + wid;

    for (int t0 = 0; t0 < 16; t0++) {
        int t = warp_global * 16 + t0;
        const float* hr = g_h + (size_t)t * NH;
        float p0 = 0.f, p1 = 0.f, p2 = 0.f, p3 = 0.f;
#pragma unroll
        for (int j = 0; j < 8; j++) {
            int col = j * 32 + lane;
            float hv = hr[col];
            p0 += hv * wg_s[col * 4 + 0];
            p1 += hv * wg_s[col * 4 + 1];
            p2 += hv * wg_s[col * 4 + 2];
            p3 += hv * wg_s[col * 4 + 3];
        }
#pragma unroll
        for (int off = 16; off > 0; off >>= 1) {
            p0 += __shfl_xor_sync(0xffffffffu, p0, off);
            p1 += __shfl_xor_sync(0xffffffffu, p1, off);
            p2 += __shfl_xor_sync(0xffffffffu, p2, off);
            p3 += __shfl_xor_sync(0xffffffffu, p3, off);
        }
        if (lane == 0) {
            int e = 0; float b = p0;
            if (p1 > b) { b = p1; e = 1; }
            if (p2 > b) { b = p2; e = 2; }
            if (p3 > b) { b = p3; e = 3; }
            // prob of argmax expert = exp(b-b) / sum exp(l-b) = 1/s
            float s = expf(p0 - b) + expf(p1 - b) + expf(p2 - b) + expf(p3 - b);
            g_gate[t] = 1.0f / s;
            g_eid[t] = e;
            g_pos[t] = atomicAdd(&g_cnt[e], 1);
        }
    }
}

// ---------------- prefix: padded per-expert offsets ----------------
__global__ void k_prefix() {
    if (threadIdx.x == 0 && blockIdx.x == 0) {
        int o = 0;
        g_off[0] = 0;
        for (int e = 0; e < NE; e++) {
            o += (g_cnt[e] + BM - 1) & ~(BM - 1);
            g_off[e + 1] = o;
        }
    }
}

__global__ void k_fill() {
    int i = blockIdx.x * 256 + threadIdx.x;
    if (i < N_TOK + NE * BM) g_perm[i] = -1;
}

__global__ void k_scatter() {
    int t = blockIdx.x * 256 + threadIdx.x;
    if (t < N_TOK) g_perm[g_off[g_eid[t]] + g_pos[t]] = t;
}

// ---------------- stage 2: out = gate * (h_gathered @ We[e] + be[e]) ----------------
__global__ void __launch_bounds__(256, 2) k_stage2(
    const float* __restrict__ We, const float* __restrict__ be,
    float* __restrict__ out)
{
    const int start = blockIdx.x * BM;
    const int total = g_off[NE];
    if (start >= total) return;   // uniform per block — safe before syncs

    int e = 0;
    while (e < NE - 1 && start >= g_off[e + 1]) e++;
    const float* W = We + (size_t)e * NH * NH;

    __shared__ __align__(16) float As[BK][BM + 4];
    __shared__ __align__(16) float Bs[BK][BN];
    __shared__ int rows_s[BM];

    const int n0 = blockIdx.y * BN;
    const int tid = threadIdx.x;
    const int tx = tid & 15;
    const int ty = tid >> 4;
    const int ar = tid >> 3;
    const int ac4 = tid & 7;
    const int br = tid >> 5;
    const int bc4 = tid & 31;

    if (tid < BM) rows_s[tid] = g_perm[start + tid];
    __syncthreads();

    unsigned long long acc[8][4];
#pragma unroll
    for (int i = 0; i < 8; i++)
#pragma unroll
        for (int j = 0; j < 4; j++) acc[i][j] = 0ull;

    for (int kt = 0; kt < NH / BK; kt++) {
#pragma unroll
        for (int i = 0; i < 4; i++) {
            int r = ar + i * 32;
            int grow = rows_s[r];
            float4 v = make_float4(0.f, 0.f, 0.f, 0.f);
            if (grow >= 0)
                v = *(const float4*)(g_h + (size_t)grow * NH + kt * BK + ac4 * 4);
            As[ac4 * 4 + 0][r] = v.x;
            As[ac4 * 4 + 1][r] = v.y;
            As[ac4 * 4 + 2][r] = v.z;
            As[ac4 * 4 + 3][r] = v.w;
        }
#pragma unroll
        for (int i = 0; i < 4; i++) {
            int kr = br + i * 8;
            *(float4*)&Bs[kr][bc4 * 4] =
                *(const float4*)(W + (size_t)(kt * BK + kr) * NH + n0 + bc4 * 4);
        }
        __syncthreads();

#pragma unroll
        for (int kk = 0; kk < BK; kk++) {
            const float4 a0 = *(const float4*)&As[kk][ty * 8];
            const float4 a1 = *(const float4*)&As[kk][ty * 8 + 4];
            const ulonglong2 bb0 = *(const ulonglong2*)&Bs[kk][tx * 8];
            const ulonglong2 bb1 = *(const ulonglong2*)&Bs[kk][tx * 8 + 4];
            unsigned long long pa;
            pa = pack2(a0.x); fma2(acc[0][0], pa, bb0.x); fma2(acc[0][1], pa, bb0.y); fma2(acc[0][2], pa, bb1.x); fma2(acc[0][3], pa, bb1.y);
            pa = pack2(a0.y); fma2(acc[1][0], pa, bb0.x); fma2(acc[1][1], pa, bb0.y); fma2(acc[1][2], pa, bb1.x); fma2(acc[1][3], pa, bb1.y);
            pa = pack2(a0.z); fma2(acc[2][0], pa, bb0.x); fma2(acc[2][1], pa, bb0.y); fma2(acc[2][2], pa, bb1.x); fma2(acc[2][3], pa, bb1.y);
            pa = pack2(a0.w); fma2(acc[3][0], pa, bb0.x); fma2(acc[3][1], pa, bb0.y); fma2(acc[3][2], pa, bb1.x); fma2(acc[3][3], pa, bb1.y);
            pa = pack2(a1.x); fma2(acc[4][0], pa, bb0.x); fma2(acc[4][1], pa, bb0.y); fma2(acc[4][2], pa, bb1.x); fma2(acc[4][3], pa, bb1.y);
            pa = pack2(a1.y); fma2(acc[5][0], pa, bb0.x); fma2(acc[5][1], pa, bb0.y); fma2(acc[5][2], pa, bb1.x); fma2(acc[5][3], pa, bb1.y);
            pa = pack2(a1.z); fma2(acc[6][0], pa, bb0.x); fma2(acc[6][1], pa, bb0.y); fma2(acc[6][2], pa, bb1.x); fma2(acc[6][3], pa, bb1.y);
            pa = pack2(a1.w); fma2(acc[7][0], pa, bb0.x); fma2(acc[7][1], pa, bb0.y); fma2(acc[7][2], pa, bb1.x); fma2(acc[7][3], pa, bb1.y);
        }
        __syncthreads();
    }

    float bias[8];
#pragma unroll
    for (int j = 0; j < 8; j++) bias[j] = be[e * NH + n0 + tx * 8 + j];

#pragma unroll
    for (int i = 0; i < 8; i++) {
        int tok = rows_s[ty * 8 + i];
        if (tok < 0) continue;
        float gmul = g_gate[tok];
        float o[8];
#pragma unroll
        for (int jp = 0; jp < 4; jp++) {
            float2 v = unpack2(acc[i][jp]);
            o[2 * jp]     = gmul * (v.x + bias[2 * jp]);
            o[2 * jp + 1] = gmul * (v.y + bias[2 * jp + 1]);
        }
        float4* dst = (float4*)(out + (size_t)tok * NH + n0 + tx * 8);
        dst[0] = make_float4(o[0], o[1], o[2], o[3]);
        dst[1] = make_float4(o[4], o[5], o[6], o[7]);
    }
}

// ---------------- launch ----------------
extern "C" void kernel_launch(void* const* d_in, const int* in_sizes, int n_in,
                              void* d_out, int out_size) {
    const float* x  = (const float*)d_in[0];   // [262144, 256]
    const float* W1 = (const float*)d_in[1];   // [256, 256]
    const float* b1 = (const float*)d_in[2];   // [256]
    const float* Wg = (const float*)d_in[3];   // [256, 4]
    const float* We = (const float*)d_in[4];   // [4, 256, 256]
    const float* be = (const float*)d_in[5];   // [4, 256]
    float* out = (float*)d_out;

    k_zero<<<1, 32>>>();
    k_stage1<<<dim3(N_TOK / BM, NH / BN), 256>>>(x, W1, b1);
    k_route<<<N_TOK / 128, 256>>>(Wg);         // 2048 blocks, 128 tokens/block (R6 bug: launched 64)
    k_prefix<<<1, 32>>>();
    k_fill<<<(N_TOK + NE * BM) / 256, 256>>>();
    k_scatter<<<N_TOK / 256, 256>>>();
    k_stage2<<<dim3(N_TOK / BM + NE, NH / BN), 256>>>(We, be, out);
}